// round 16
// baseline (speedup 1.0000x reference)
#include <cuda_runtime.h>
#include <math.h>
#include <stdint.h>

#define NA 50000
#define GD 15
#define NC (GD*GD*GD)
#define MP 2000000
#define CAP_A 96
#define CAP_W 768
#define CAP_C 64
#define NBE_A ((NA + 31) / 32)     // 1563 emit blocks (32 atoms)
#define NBE_W ((NC + 31) / 32)     // 106 emit blocks (32 cells)
#define NFA   NBE_A                // fine bins over atoms (32 each)
#define NCA   ((NA + 1023) / 1024) // 49 coarse bins over atoms
#define NFW   NBE_W                // fine bins over cells (32 each)
#define NB_TAIL 512
#define OWN_TAB 6144

// ---------------- scratch (no allocs; zero-init at load) ----------------
__device__ int    g_cnt[NC];                       // zero at replay start (re-zeroed in emit tail)
__device__ float4 g_cell4[(size_t)NC * CAP_C];     // unsorted per-cell (x,y,z,idbits)
__device__ float4 g_sp4[(size_t)NC * CAP_C];       // id-sorted per-cell
__device__ int    g_akept[NA];
__device__ int    g_wkept[NC];
__device__ int    g_fineA[NFA];                    // zeroed in k_assign each replay
__device__ int    g_coarseA[NCA];
__device__ int    g_fineW[NFW];
__device__ float4 g_scrA[(size_t)NA * CAP_A];      // per-atom surround staging
__device__ float4 g_scrW[(size_t)NC * CAP_W];      // per-cell within staging

__constant__ int c_off[13][3] = {
  {-1,0,0},{-1,-1,0},{0,-1,0},{1,-1,0},{-1,1,-1},{0,1,-1},{1,1,-1},
  {-1,0,-1},{0,0,-1},{1,0,-1},{-1,-1,-1},{0,-1,-1},{1,-1,-1}};

// ---------------- helpers ----------------
__device__ __forceinline__ int cellcoord(double v) {
  const double inv = 1.0/80.0;
  double f = __dmul_rn(v, inv);
  f = f - floor(f);
  if (f >= 1.0) f -= 1.0;
  if (f <  0.0) f += 1.0;
  return (int)floor(__dmul_rn(f, (double)GD));
}

__device__ __forceinline__ bool keep_pair(float ax, float ay, float az,
                                          float bx, float by, float bz,
                                          float fsx, float fsy, float fsz,
                                          float& dx, float& dy, float& dz) {
  dx = (ax - bx) + fsx;
  dy = (ay - by) + fsy;
  dz = (az - bz) + fsz;
  float sq = dx*dx + dy*dy + dz*dz;
  if (sq <= 27.0290f) return true;     // (5.2 - 1e-3)^2
  if (sq >  27.0510f) return false;    // (5.2 + 1e-3)^2
  double ddx = __dadd_rn(__dsub_rn((double)ax, (double)bx), (double)fsx);
  double ddy = __dadd_rn(__dsub_rn((double)ay, (double)by), (double)fsy);
  double ddz = __dadd_rn(__dsub_rn((double)az, (double)bz), (double)fsz);
  double dsq = __dadd_rn(__dadd_rn(__dmul_rn(ddx,ddx), __dmul_rn(ddy,ddy)), __dmul_rn(ddz,ddz));
  return sqrt(dsq) <= 5.2;
}

__device__ __forceinline__ int warp_sum_bcast(int v) {
  #pragma unroll
  for (int o = 16; o >= 1; o >>= 1) v += __shfl_down_sync(0xffffffffu, v, o);
  return __shfl_sync(0xffffffffu, v, 0);
}

// ---------------- 1. assign: cell id + fixed-stride staging + bin reset -------
__global__ void k_assign(const float* __restrict__ coords) {
  int i = blockIdx.x*blockDim.x + threadIdx.x;
  if (i < NFA)                  g_fineA[i] = 0;
  else if (i < NFA + NCA)       g_coarseA[i - NFA] = 0;
  else if (i < NFA + NCA + NFW) g_fineW[i - NFA - NCA] = 0;
  if (i >= NA) return;
  float x = coords[3*i+0], y = coords[3*i+1], z = coords[3*i+2];
  int cx = cellcoord((double)x);
  int cy = cellcoord((double)y);
  int cz = cellcoord((double)z);
  int f = (cx*GD + cy)*GD + cz;
  int slot = atomicAdd(&g_cnt[f], 1);
  if (slot < CAP_C)
    g_cell4[f*CAP_C + slot] = make_float4(x, y, z, __int_as_float(i));
}

// ---------------- 2. per-cell id rank-sort (stable = ascending id) ------------
__global__ void __launch_bounds__(256) k_sortcell() {
  __shared__ float4 sc[8][CAP_C];
  int w = (blockIdx.x*blockDim.x + threadIdx.x) >> 5;
  int lane = threadIdx.x & 31;
  int wl = threadIdx.x >> 5;
  if (w >= NC) return;
  int n = g_cnt[w]; if (n > CAP_C) n = CAP_C;
  int s = w * CAP_C;
  for (int k = lane; k < n; k += 32) sc[wl][k] = g_cell4[s+k];
  __syncwarp();
  for (int k = lane; k < n; k += 32) {
    float4 v = sc[wl][k];
    int id = __float_as_int(v.w);
    int rank = 0;
    for (int m = 0; m < n; m++) rank += (__float_as_int(sc[wl][m].w) < id);
    g_sp4[s+rank] = v;
  }
}

// ---------------- 3. pairs: one block per cell, smem candidates ----------------
// candidate word packs: bits[0:16) atom id, bits[16:22) shift code
__global__ void __launch_bounds__(256) k_pairs() {
  const unsigned FULL = 0xffffffffu;
  int tid = threadIdx.x, lane = tid & 31, wl = tid >> 5;
  int c = blockIdx.x;

  __shared__ float4 s_cand[13*CAP_C];   // 13 neighbor segments, contiguous
  __shared__ float4 s_own[CAP_C];       // own cell
  __shared__ int    s_pre[13], s_end[13], s_gbase[13], s_shp[13];
  __shared__ int    s_total, s_nown;

  int cz = c % GD, cy = (c / GD) % GD, cx = c / (GD*GD);

  if (wl == 0) {
    int segC = 0, segB = 0, shp = 0;
    if (lane < 13) {
      int nx = cx + c_off[lane][0], ny = cy + c_off[lane][1], nz = cz + c_off[lane][2];
      int sx = 0, sy = 0, sz = 0;
      if (nx < 0) { nx += GD; sx = 1; } else if (nx >= GD) { nx -= GD; sx = -1; }
      if (ny < 0) { ny += GD; sy = 1; } else if (ny >= GD) { ny -= GD; sy = -1; }
      if (nz < 0) { nz += GD; sz = 1; } else if (nz >= GD) { nz -= GD; sz = -1; }
      int nc = (nx*GD + ny)*GD + nz;
      segB = nc * CAP_C;
      segC = g_cnt[nc]; if (segC > CAP_C) segC = CAP_C;
      shp = (sx+1) | ((sy+1)<<2) | ((sz+1)<<4);
    }
    int pre = segC;
    #pragma unroll
    for (int o = 1; o < 16; o <<= 1) {
      int y = __shfl_up_sync(FULL, pre, o);
      if (lane >= o) pre += y;
    }
    int total = __shfl_sync(FULL, pre, 12);
    if (lane < 13) {
      s_pre[lane] = pre - segC;
      s_end[lane] = pre;
      s_gbase[lane] = segB;
      s_shp[lane] = shp << 16;
    }
    if (lane == 0) {
      s_total = total;
      int n = g_cnt[c]; if (n > CAP_C) n = CAP_C;
      s_nown = n;
    }
  }
  __syncthreads();

  int total = s_total, nown = s_nown;
  // segment-parallel cooperative load: warp w loads segments w, w+8 (no search)
  for (int o = wl; o < 13; o += 8) {
    int d0  = s_pre[o];
    int cnt = s_end[o] - d0;
    int gb  = s_gbase[o];
    int shp = s_shp[o];
    for (int k = lane; k < cnt; k += 32) {
      float4 v = g_sp4[gb + k];
      v.w = __int_as_float(__float_as_int(v.w) | shp);
      s_cand[d0 + k] = v;
    }
  }
  for (int t = tid; t < nown; t += 256)
    s_own[t] = g_sp4[c*CAP_C + t];
  __syncthreads();

  // Phase A: surround pairs; warp processes TWO atoms (wl, wl+8) per candidate
  // chunk — one candidate load + decode serves both keep tests.
  for (int ib = wl; ib < nown; ib += 16) {
    int iA = ib, iB = ib + 8;
    bool hasB = (iB < nown);
    float4 av1 = s_own[iA];
    float4 av2 = hasB ? s_own[iB] : av1;
    int a1 = __float_as_int(av1.w);
    int a2 = __float_as_int(av2.w);
    float4* scr1 = &g_scrA[(size_t)a1 * CAP_A];
    float4* scr2 = &g_scrA[(size_t)a2 * CAP_A];
    int wp1 = 0, wp2 = 0;
    for (int t0 = 0; t0 < total; t0 += 32) {
      int t = t0 + lane;
      bool in = (t < total);
      float4 v;
      float fsx = 0.f, fsy = 0.f, fsz = 0.f;
      int bid = 0;
      if (in) {
        v = s_cand[t];
        int pw = __float_as_int(v.w);
        int shp = pw >> 16;
        fsx = (float)((shp      & 3) - 1) * 80.0f;
        fsy = (float)(((shp>>2) & 3) - 1) * 80.0f;
        fsz = (float)(((shp>>4) & 3) - 1) * 80.0f;
        bid = pw & 0xFFFF;
      }
      bool kp1 = false, kp2 = false;
      float dx1=0.f,dy1=0.f,dz1=0.f, dx2=0.f,dy2=0.f,dz2=0.f;
      if (in) {
        kp1 = keep_pair(av1.x, av1.y, av1.z, v.x, v.y, v.z, fsx, fsy, fsz, dx1, dy1, dz1);
        if (hasB)
          kp2 = keep_pair(av2.x, av2.y, av2.z, v.x, v.y, v.z, fsx, fsy, fsz, dx2, dy2, dz2);
      }
      unsigned m1 = __ballot_sync(FULL, kp1);
      if (kp1) {
        int p = wp1 + __popc(m1 & ((1u << lane) - 1u));
        scr1[p] = make_float4(__int_as_float(bid), dx1, dy1, dz1);
      }
      wp1 += __popc(m1);
      unsigned m2 = __ballot_sync(FULL, kp2);
      if (kp2) {
        int p = wp2 + __popc(m2 & ((1u << lane) - 1u));
        scr2[p] = make_float4(__int_as_float(bid), dx2, dy2, dz2);
      }
      wp2 += __popc(m2);
    }
    if (lane == 0) {
      g_akept[a1] = wp1;
      atomicAdd(&g_fineA[a1 >> 5], wp1);
      atomicAdd(&g_coarseA[a1 >> 10], wp1);
      if (hasB) {
        g_akept[a2] = wp2;
        atomicAdd(&g_fineA[a2 >> 5], wp2);
        atomicAdd(&g_coarseA[a2 >> 10], wp2);
      }
    }
  }

  // Phase B: within-cell pairs on warp 7 (least-loaded in Phase A), tril order
  if (wl == 7) {
    int n = nown;
    int T = n*(n-1)/2;
    float4* scr = &g_scrW[(size_t)c * CAP_W];
    int wp = 0;
    for (int t0 = 0; t0 < T; t0 += 32) {
      int t = t0 + lane;
      bool kp = false; int ij = 0; float dx = 0.f, dy = 0.f, dz = 0.f;
      if (t < T) {
        int i = (int)((1.0f + sqrtf(8.0f*(float)t + 1.0f)) * 0.5f);
        while (i*(i-1)/2 > t) i--;
        while ((i+1)*i/2 <= t) i++;
        int j = t - i*(i-1)/2;
        float4 va = s_own[i];
        float4 vb = s_own[j];
        kp = keep_pair(va.x, va.y, va.z, vb.x, vb.y, vb.z, 0.f, 0.f, 0.f, dx, dy, dz);
        ij = i | (j << 8);
      }
      unsigned m = __ballot_sync(FULL, kp);
      if (kp) {
        int p = wp + __popc(m & ((1u << lane) - 1u));
        scr[p] = make_float4(__int_as_float(ij), dx, dy, dz);
      }
      wp += __popc(m);
    }
    if (lane == 0) {
      g_wkept[c] = wp;
      atomicAdd(&g_fineW[c >> 5], wp);
    }
  }
}

// ---------------- 4. emit: thread-per-pair (4-way), parallel prologue ----------
__device__ __forceinline__ void emit_one(float* __restrict__ out, int p,
                                         float fa, float fb,
                                         float dx, float dy, float dz) {
  out[p]        = fa;
  out[MP + p]   = fb;
  out[2*MP + p] = sqrtf(dx*dx + dy*dy + dz*dz);
  out[3*MP + 3*p + 0] = dx;
  out[3*MP + 3*p + 1] = dy;
  out[3*MP + 3*p + 2] = dz;
  out[6*MP + p] = 1.0f;
}

// zero flat float range [s, e); e % 4 == 0; gt/gs = global tail thread id/stride
__device__ __forceinline__ void zero_range(float* __restrict__ out, int s, int e,
                                           int gt, int gs) {
  int s4 = (s + 3) & ~3; if (s4 > e) s4 = e;
  if (gt < s4 - s) out[s + gt] = 0.f;
  float4* o4 = (float4*)out;
  const float4 z = make_float4(0.f, 0.f, 0.f, 0.f);
  for (int i = (s4 >> 2) + gt; i < (e >> 2); i += gs) o4[i] = z;
}

__global__ void __launch_bounds__(256) k_emit(float* __restrict__ out) {
  const unsigned FULL = 0xffffffffu;
  int lane = threadIdx.x & 31;
  int wl = threadIdx.x >> 5;
  int b = blockIdx.x;
  __shared__ unsigned char sh_owner[OWN_TAB];
  __shared__ int sh_P[33];     // exclusive prefix of the 32 counts; P[32] = T
  __shared__ int sh_base;
  __shared__ int sh_useTab;

  if (b < NBE_A + NBE_W) {
    bool isA = (b < NBE_A);
    int eb = isA ? b : (b - NBE_A);
    int u0 = eb * 32;                 // first atom/cell of this block

    // prologue: warp 0 -> global base; warp 1 -> counts scan
    if (wl == 0) {
      int acc = 0;
      if (isA) {
        int cb = b >> 5;
        for (int q = lane; q < NCA; q += 32) acc += (q < cb) ? g_coarseA[q] : 0;
        if (lane < (b & 31)) acc += g_fineA[(cb << 5) + lane];
      } else {
        for (int q = lane; q < NCA; q += 32) acc += g_coarseA[q];          // totalS
        for (int q = lane; q < NFW; q += 32) acc += (q < eb) ? g_fineW[q] : 0;
      }
      int base = warp_sum_bcast(acc);
      if (lane == 0) sh_base = base;
    } else if (wl == 1) {
      int u = u0 + lane;
      int cnt = isA ? ((u < NA) ? g_akept[u] : 0)
                    : ((u < NC) ? g_wkept[u] : 0);
      int pre = cnt;
      #pragma unroll
      for (int o = 1; o < 32; o <<= 1) {
        int y = __shfl_up_sync(FULL, pre, o);
        if (lane >= o) pre += y;
      }
      sh_P[lane + 1] = pre;
      if (lane == 0) sh_P[0] = 0;
      if (lane == 31) sh_useTab = (pre <= OWN_TAB);
    }
    __syncthreads();

    // parallel owner-table fill: warp w fills entries for items 4w..4w+3
    bool useTab = (sh_useTab != 0) || isA;   // surround always fits (T<=3072)
    if (useTab) {
      #pragma unroll
      for (int r = 0; r < 4; r++) {
        int li = wl*4 + r;
        int s0 = sh_P[li], e0 = sh_P[li+1];
        for (int t = s0 + lane; t < e0; t += 32)
          sh_owner[t] = (unsigned char)li;
      }
    }
    __syncthreads();

    int T = sh_P[32];
    int base = sh_base;

    // 4-way thread-per-pair
    for (int t = threadIdx.x; t < T; t += 1024) {
      int  tt[4]; bool hv[4]; int li[4];
      #pragma unroll
      for (int q = 0; q < 4; q++) {
        tt[q] = t + q*256;
        hv[q] = (tt[q] < T);
      }
      #pragma unroll
      for (int q = 0; q < 4; q++) {
        if (!hv[q]) { li[q] = 0; continue; }
        if (useTab) li[q] = sh_owner[tt[q]];
        else {
          int lo = 0, hi = 32;
          #pragma unroll
          for (int s = 0; s < 5; s++) { int m = (lo+hi)>>1; if (sh_P[m] <= tt[q]) lo = m; else hi = m; }
          li[q] = lo;
        }
      }
      float4 v[4];
      #pragma unroll
      for (int q = 0; q < 4; q++) {
        if (!hv[q]) continue;
        int k = tt[q] - sh_P[li[q]];
        int u = u0 + li[q];
        v[q] = isA ? g_scrA[(size_t)u * CAP_A + k]
                   : g_scrW[(size_t)u * CAP_W + k];
      }
      #pragma unroll
      for (int q = 0; q < 4; q++) {
        if (!hv[q]) continue;
        int u = u0 + li[q];
        if (isA) {
          emit_one(out, base + tt[q], (float)u, (float)__float_as_int(v[q].x),
                   v[q].y, v[q].z, v[q].w);
        } else {
          int ij = __float_as_int(v[q].x);
          int s4 = u * CAP_C;
          float fa = (float)__float_as_int(g_sp4[s4 + (ij & 0xff)].w);
          float fb = (float)__float_as_int(g_sp4[s4 + (ij >> 8)].w);
          emit_one(out, base + tt[q], fa, fb, v[q].y, v[q].z, v[q].w);
        }
      }
    }
  } else {
    // ---- tail (last): zero padded regions + re-zero g_cnt for next replay
    int tb = b - NBE_A - NBE_W;             // 0..NB_TAIL-1
    int zi = tb*blockDim.x + threadIdx.x;
    if (zi < NC) g_cnt[zi] = 0;
    __shared__ int sh_total;
    if (wl == 0) {
      int acc = 0;
      for (int q = lane; q < NCA; q += 32) acc += g_coarseA[q];
      for (int q = lane; q < NFW; q += 32) acc += g_fineW[q];
      int tot = warp_sum_bcast(acc);
      if (lane == 0) sh_total = tot;
    }
    __syncthreads();
    int total = sh_total;
    int gt = tb*blockDim.x + threadIdx.x;
    int gs = NB_TAIL * blockDim.x;
    zero_range(out,        total,   MP,   gt, gs);
    zero_range(out,   MP + total, 2*MP,   gt, gs);
    zero_range(out, 2*MP + total, 3*MP,   gt, gs);
    zero_range(out, 3*MP + 3*total, 6*MP, gt, gs);
    zero_range(out, 6*MP + total, 7*MP,   gt, gs);
  }
}

// ---------------- launch ----------------
extern "C" void kernel_launch(void* const* d_in, const int* in_sizes, int n_in,
                              void* d_out, int out_size) {
  const float* coords = nullptr;
  for (int i = 0; i < n_in; i++)
    if (in_sizes[i] == 3*NA) coords = (const float*)d_in[i];
  float* out = (float*)d_out;

  k_assign  <<<(NA + 255)/256, 256>>>(coords);            // cells + staging + bin reset
  k_sortcell<<<(NC + 7)/8, 256>>>();                      // per-cell id sort -> g_sp4
  k_pairs   <<<NC, 256>>>();                              // dual-atom smem pairs
  k_emit    <<<NBE_A + NBE_W + NB_TAIL, 256>>>(out);      // 4-way emit + flat-range tail
}

// round 17
// speedup vs baseline: 1.0075x; 1.0075x over previous
#include <cuda_runtime.h>
#include <math.h>
#include <stdint.h>

#define NA 50000
#define GD 15
#define NC (GD*GD*GD)
#define MP 2000000
#define CAP_A 96
#define CAP_W 768
#define CAP_C 64
#define NBE_A ((NA + 31) / 32)     // 1563 emit blocks (32 atoms)
#define NBE_W ((NC + 31) / 32)     // 106 emit blocks (32 cells)
#define NFA   NBE_A                // fine bins over atoms (32 each)
#define NCA   ((NA + 1023) / 1024) // 49 coarse bins over atoms
#define NFW   NBE_W                // fine bins over cells (32 each)
#define NB_TAIL 512
#define OWN_TAB 6144

// ---------------- scratch (no allocs; zero-init at load) ----------------
__device__ int    g_cnt[NC];                       // zero at replay start (re-zeroed in emit tail)
__device__ float4 g_cell4[(size_t)NC * CAP_C];     // unsorted per-cell (x,y,z,idbits)
__device__ float4 g_sp4[(size_t)NC * CAP_C];       // id-sorted per-cell
__device__ int    g_akept[NA];
__device__ int    g_wkept[NC];
__device__ int    g_fineA[NFA];                    // zeroed in k_assign each replay
__device__ int    g_coarseA[NCA];
__device__ int    g_fineW[NFW];
__device__ float4 g_scrA[(size_t)NA * CAP_A];      // per-atom surround staging
__device__ float4 g_scrW[(size_t)NC * CAP_W];      // per-cell within staging

__constant__ int c_off[13][3] = {
  {-1,0,0},{-1,-1,0},{0,-1,0},{1,-1,0},{-1,1,-1},{0,1,-1},{1,1,-1},
  {-1,0,-1},{0,0,-1},{1,0,-1},{-1,-1,-1},{0,-1,-1},{1,-1,-1}};

// ---------------- helpers ----------------
__device__ __forceinline__ int cellcoord(double v) {
  const double inv = 1.0/80.0;
  double f = __dmul_rn(v, inv);
  f = f - floor(f);
  if (f >= 1.0) f -= 1.0;
  if (f <  0.0) f += 1.0;
  return (int)floor(__dmul_rn(f, (double)GD));
}

__device__ __forceinline__ bool keep_pair(float ax, float ay, float az,
                                          float bx, float by, float bz,
                                          float fsx, float fsy, float fsz,
                                          float& dx, float& dy, float& dz) {
  dx = (ax - bx) + fsx;
  dy = (ay - by) + fsy;
  dz = (az - bz) + fsz;
  float sq = dx*dx + dy*dy + dz*dz;
  if (sq <= 27.0290f) return true;     // (5.2 - 1e-3)^2
  if (sq >  27.0510f) return false;    // (5.2 + 1e-3)^2
  double ddx = __dadd_rn(__dsub_rn((double)ax, (double)bx), (double)fsx);
  double ddy = __dadd_rn(__dsub_rn((double)ay, (double)by), (double)fsy);
  double ddz = __dadd_rn(__dsub_rn((double)az, (double)bz), (double)fsz);
  double dsq = __dadd_rn(__dadd_rn(__dmul_rn(ddx,ddx), __dmul_rn(ddy,ddy)), __dmul_rn(ddz,ddz));
  return sqrt(dsq) <= 5.2;
}

__device__ __forceinline__ int warp_sum_bcast(int v) {
  #pragma unroll
  for (int o = 16; o >= 1; o >>= 1) v += __shfl_down_sync(0xffffffffu, v, o);
  return __shfl_sync(0xffffffffu, v, 0);
}

// ---------------- 1. assign: cell id + fixed-stride staging + bin reset -------
__global__ void k_assign(const float* __restrict__ coords) {
  int i = blockIdx.x*blockDim.x + threadIdx.x;
  if (i < NFA)                  g_fineA[i] = 0;
  else if (i < NFA + NCA)       g_coarseA[i - NFA] = 0;
  else if (i < NFA + NCA + NFW) g_fineW[i - NFA - NCA] = 0;
  if (i >= NA) return;
  float x = coords[3*i+0], y = coords[3*i+1], z = coords[3*i+2];
  int cx = cellcoord((double)x);
  int cy = cellcoord((double)y);
  int cz = cellcoord((double)z);
  int f = (cx*GD + cy)*GD + cz;
  int slot = atomicAdd(&g_cnt[f], 1);
  if (slot < CAP_C)
    g_cell4[f*CAP_C + slot] = make_float4(x, y, z, __int_as_float(i));
}

// ---------------- 2. per-cell id rank-sort (stable = ascending id) ------------
__global__ void __launch_bounds__(256) k_sortcell() {
  __shared__ float4 sc[8][CAP_C];
  int w = (blockIdx.x*blockDim.x + threadIdx.x) >> 5;
  int lane = threadIdx.x & 31;
  int wl = threadIdx.x >> 5;
  if (w >= NC) return;
  int n = g_cnt[w]; if (n > CAP_C) n = CAP_C;
  int s = w * CAP_C;
  for (int k = lane; k < n; k += 32) sc[wl][k] = g_cell4[s+k];
  __syncwarp();
  for (int k = lane; k < n; k += 32) {
    float4 v = sc[wl][k];
    int id = __float_as_int(v.w);
    int rank = 0;
    for (int m = 0; m < n; m++) rank += (__float_as_int(sc[wl][m].w) < id);
    g_sp4[s+rank] = v;
  }
}

// ---------------- 3. pairs: one block per cell, smem candidates ----------------
// candidate word packs: bits[0:16) atom id, bits[16:22) shift code
__global__ void __launch_bounds__(256) k_pairs() {
  const unsigned FULL = 0xffffffffu;
  int tid = threadIdx.x, lane = tid & 31, wl = tid >> 5;
  int c = blockIdx.x;

  __shared__ float4 s_cand[13*CAP_C];   // 13 neighbor segments, contiguous
  __shared__ float4 s_own[CAP_C];       // own cell
  __shared__ int    s_pre[13], s_end[13], s_gbase[13], s_shp[13];
  __shared__ int    s_total, s_nown;

  int cz = c % GD, cy = (c / GD) % GD, cx = c / (GD*GD);

  if (wl == 0) {
    int segC = 0, segB = 0, shp = 0;
    if (lane < 13) {
      int nx = cx + c_off[lane][0], ny = cy + c_off[lane][1], nz = cz + c_off[lane][2];
      int sx = 0, sy = 0, sz = 0;
      if (nx < 0) { nx += GD; sx = 1; } else if (nx >= GD) { nx -= GD; sx = -1; }
      if (ny < 0) { ny += GD; sy = 1; } else if (ny >= GD) { ny -= GD; sy = -1; }
      if (nz < 0) { nz += GD; sz = 1; } else if (nz >= GD) { nz -= GD; sz = -1; }
      int nc = (nx*GD + ny)*GD + nz;
      segB = nc * CAP_C;
      segC = g_cnt[nc]; if (segC > CAP_C) segC = CAP_C;
      shp = (sx+1) | ((sy+1)<<2) | ((sz+1)<<4);
    }
    int pre = segC;
    #pragma unroll
    for (int o = 1; o < 16; o <<= 1) {
      int y = __shfl_up_sync(FULL, pre, o);
      if (lane >= o) pre += y;
    }
    int total = __shfl_sync(FULL, pre, 12);
    if (lane < 13) {
      s_pre[lane] = pre - segC;
      s_end[lane] = pre;
      s_gbase[lane] = segB;
      s_shp[lane] = shp << 16;
    }
    if (lane == 0) {
      s_total = total;
      int n = g_cnt[c]; if (n > CAP_C) n = CAP_C;
      s_nown = n;
    }
  }
  __syncthreads();

  int total = s_total, nown = s_nown;
  // segment-parallel cooperative load: warp w loads segments w, w+8 (no search)
  for (int o = wl; o < 13; o += 8) {
    int d0  = s_pre[o];
    int cnt = s_end[o] - d0;
    int gb  = s_gbase[o];
    int shp = s_shp[o];
    for (int k = lane; k < cnt; k += 32) {
      float4 v = g_sp4[gb + k];
      v.w = __int_as_float(__float_as_int(v.w) | shp);
      s_cand[d0 + k] = v;
    }
  }
  for (int t = tid; t < nown; t += 256)
    s_own[t] = g_sp4[c*CAP_C + t];
  __syncthreads();

  // Phase A: surround pairs; warp processes TWO atoms (wl, wl+8) per candidate
  // chunk — one candidate load + decode serves both keep tests.
  for (int ib = wl; ib < nown; ib += 16) {
    int iA = ib, iB = ib + 8;
    bool hasB = (iB < nown);
    float4 av1 = s_own[iA];
    float4 av2 = hasB ? s_own[iB] : av1;
    int a1 = __float_as_int(av1.w);
    int a2 = __float_as_int(av2.w);
    float4* scr1 = &g_scrA[(size_t)a1 * CAP_A];
    float4* scr2 = &g_scrA[(size_t)a2 * CAP_A];
    int wp1 = 0, wp2 = 0;
    for (int t0 = 0; t0 < total; t0 += 32) {
      int t = t0 + lane;
      bool in = (t < total);
      float4 v;
      float fsx = 0.f, fsy = 0.f, fsz = 0.f;
      int bid = 0;
      if (in) {
        v = s_cand[t];
        int pw = __float_as_int(v.w);
        int shp = pw >> 16;
        fsx = (float)((shp      & 3) - 1) * 80.0f;
        fsy = (float)(((shp>>2) & 3) - 1) * 80.0f;
        fsz = (float)(((shp>>4) & 3) - 1) * 80.0f;
        bid = pw & 0xFFFF;
      }
      bool kp1 = false, kp2 = false;
      float dx1=0.f,dy1=0.f,dz1=0.f, dx2=0.f,dy2=0.f,dz2=0.f;
      if (in) {
        kp1 = keep_pair(av1.x, av1.y, av1.z, v.x, v.y, v.z, fsx, fsy, fsz, dx1, dy1, dz1);
        if (hasB)
          kp2 = keep_pair(av2.x, av2.y, av2.z, v.x, v.y, v.z, fsx, fsy, fsz, dx2, dy2, dz2);
      }
      unsigned m1 = __ballot_sync(FULL, kp1);
      if (kp1) {
        int p = wp1 + __popc(m1 & ((1u << lane) - 1u));
        scr1[p] = make_float4(__int_as_float(bid), dx1, dy1, dz1);
      }
      wp1 += __popc(m1);
      unsigned m2 = __ballot_sync(FULL, kp2);
      if (kp2) {
        int p = wp2 + __popc(m2 & ((1u << lane) - 1u));
        scr2[p] = make_float4(__int_as_float(bid), dx2, dy2, dz2);
      }
      wp2 += __popc(m2);
    }
    if (lane == 0) {
      g_akept[a1] = wp1;
      atomicAdd(&g_fineA[a1 >> 5], wp1);
      atomicAdd(&g_coarseA[a1 >> 10], wp1);
      if (hasB) {
        g_akept[a2] = wp2;
        atomicAdd(&g_fineA[a2 >> 5], wp2);
        atomicAdd(&g_coarseA[a2 >> 10], wp2);
      }
    }
  }

  // Phase B: within-cell pairs on warp 7 (least-loaded in Phase A), tril order
  if (wl == 7) {
    int n = nown;
    int T = n*(n-1)/2;
    float4* scr = &g_scrW[(size_t)c * CAP_W];
    int wp = 0;
    for (int t0 = 0; t0 < T; t0 += 32) {
      int t = t0 + lane;
      bool kp = false; int ij = 0; float dx = 0.f, dy = 0.f, dz = 0.f;
      if (t < T) {
        int i = (int)((1.0f + sqrtf(8.0f*(float)t + 1.0f)) * 0.5f);
        while (i*(i-1)/2 > t) i--;
        while ((i+1)*i/2 <= t) i++;
        int j = t - i*(i-1)/2;
        float4 va = s_own[i];
        float4 vb = s_own[j];
        kp = keep_pair(va.x, va.y, va.z, vb.x, vb.y, vb.z, 0.f, 0.f, 0.f, dx, dy, dz);
        ij = i | (j << 8);
      }
      unsigned m = __ballot_sync(FULL, kp);
      if (kp) {
        int p = wp + __popc(m & ((1u << lane) - 1u));
        scr[p] = make_float4(__int_as_float(ij), dx, dy, dz);
      }
      wp += __popc(m);
    }
    if (lane == 0) {
      g_wkept[c] = wp;
      atomicAdd(&g_fineW[c >> 5], wp);
    }
  }
}

// ---------------- 4. emit: thread-per-pair (4-way), parallel prologue ----------
__device__ __forceinline__ void emit_one(float* __restrict__ out, int p,
                                         float fa, float fb,
                                         float dx, float dy, float dz) {
  out[p]        = fa;
  out[MP + p]   = fb;
  out[2*MP + p] = sqrtf(dx*dx + dy*dy + dz*dz);
  out[3*MP + 3*p + 0] = dx;
  out[3*MP + 3*p + 1] = dy;
  out[3*MP + 3*p + 2] = dz;
  out[6*MP + p] = 1.0f;
}

// zero flat float range [s, e); e % 4 == 0; gt/gs = global tail thread id/stride
__device__ __forceinline__ void zero_range(float* __restrict__ out, int s, int e,
                                           int gt, int gs) {
  int s4 = (s + 3) & ~3; if (s4 > e) s4 = e;
  if (gt < s4 - s) out[s + gt] = 0.f;
  float4* o4 = (float4*)out;
  const float4 z = make_float4(0.f, 0.f, 0.f, 0.f);
  for (int i = (s4 >> 2) + gt; i < (e >> 2); i += gs) o4[i] = z;
}

__global__ void __launch_bounds__(256) k_emit(float* __restrict__ out) {
  const unsigned FULL = 0xffffffffu;
  int lane = threadIdx.x & 31;
  int wl = threadIdx.x >> 5;
  int b = blockIdx.x;
  __shared__ unsigned char sh_owner[OWN_TAB];
  __shared__ int sh_P[33];     // exclusive prefix of the 32 counts; P[32] = T
  __shared__ int sh_base;
  __shared__ int sh_useTab;

  if (b < NBE_A + NBE_W) {
    bool isA = (b < NBE_A);
    int eb = isA ? b : (b - NBE_A);
    int u0 = eb * 32;                 // first atom/cell of this block

    // prologue: warp 0 -> global base; warp 1 -> counts scan
    if (wl == 0) {
      int acc = 0;
      if (isA) {
        int cb = b >> 5;
        for (int q = lane; q < NCA; q += 32) acc += (q < cb) ? g_coarseA[q] : 0;
        if (lane < (b & 31)) acc += g_fineA[(cb << 5) + lane];
      } else {
        for (int q = lane; q < NCA; q += 32) acc += g_coarseA[q];          // totalS
        for (int q = lane; q < NFW; q += 32) acc += (q < eb) ? g_fineW[q] : 0;
      }
      int base = warp_sum_bcast(acc);
      if (lane == 0) sh_base = base;
    } else if (wl == 1) {
      int u = u0 + lane;
      int cnt = isA ? ((u < NA) ? g_akept[u] : 0)
                    : ((u < NC) ? g_wkept[u] : 0);
      int pre = cnt;
      #pragma unroll
      for (int o = 1; o < 32; o <<= 1) {
        int y = __shfl_up_sync(FULL, pre, o);
        if (lane >= o) pre += y;
      }
      sh_P[lane + 1] = pre;
      if (lane == 0) sh_P[0] = 0;
      if (lane == 31) sh_useTab = (pre <= OWN_TAB);
    }
    __syncthreads();

    // parallel owner-table fill: warp w fills entries for items 4w..4w+3
    bool useTab = (sh_useTab != 0) || isA;   // surround always fits (T<=3072)
    if (useTab) {
      #pragma unroll
      for (int r = 0; r < 4; r++) {
        int li = wl*4 + r;
        int s0 = sh_P[li], e0 = sh_P[li+1];
        for (int t = s0 + lane; t < e0; t += 32)
          sh_owner[t] = (unsigned char)li;
      }
    }
    __syncthreads();

    int T = sh_P[32];
    int base = sh_base;

    // 4-way thread-per-pair
    for (int t = threadIdx.x; t < T; t += 1024) {
      int  tt[4]; bool hv[4]; int li[4];
      #pragma unroll
      for (int q = 0; q < 4; q++) {
        tt[q] = t + q*256;
        hv[q] = (tt[q] < T);
      }
      #pragma unroll
      for (int q = 0; q < 4; q++) {
        if (!hv[q]) { li[q] = 0; continue; }
        if (useTab) li[q] = sh_owner[tt[q]];
        else {
          int lo = 0, hi = 32;
          #pragma unroll
          for (int s = 0; s < 5; s++) { int m = (lo+hi)>>1; if (sh_P[m] <= tt[q]) lo = m; else hi = m; }
          li[q] = lo;
        }
      }
      float4 v[4];
      #pragma unroll
      for (int q = 0; q < 4; q++) {
        if (!hv[q]) continue;
        int k = tt[q] - sh_P[li[q]];
        int u = u0 + li[q];
        v[q] = isA ? g_scrA[(size_t)u * CAP_A + k]
                   : g_scrW[(size_t)u * CAP_W + k];
      }
      #pragma unroll
      for (int q = 0; q < 4; q++) {
        if (!hv[q]) continue;
        int u = u0 + li[q];
        if (isA) {
          emit_one(out, base + tt[q], (float)u, (float)__float_as_int(v[q].x),
                   v[q].y, v[q].z, v[q].w);
        } else {
          int ij = __float_as_int(v[q].x);
          int s4 = u * CAP_C;
          float fa = (float)__float_as_int(g_sp4[s4 + (ij & 0xff)].w);
          float fb = (float)__float_as_int(g_sp4[s4 + (ij >> 8)].w);
          emit_one(out, base + tt[q], fa, fb, v[q].y, v[q].z, v[q].w);
        }
      }
    }
  } else {
    // ---- tail (last): zero padded regions + re-zero g_cnt for next replay
    int tb = b - NBE_A - NBE_W;             // 0..NB_TAIL-1
    int zi = tb*blockDim.x + threadIdx.x;
    if (zi < NC) g_cnt[zi] = 0;
    __shared__ int sh_total;
    if (wl == 0) {
      int acc = 0;
      for (int q = lane; q < NCA; q += 32) acc += g_coarseA[q];
      for (int q = lane; q < NFW; q += 32) acc += g_fineW[q];
      int tot = warp_sum_bcast(acc);
      if (lane == 0) sh_total = tot;
    }
    __syncthreads();
    int total = sh_total;
    int gt = tb*blockDim.x + threadIdx.x;
    int gs = NB_TAIL * blockDim.x;
    zero_range(out,        total,   MP,   gt, gs);
    zero_range(out,   MP + total, 2*MP,   gt, gs);
    zero_range(out, 2*MP + total, 3*MP,   gt, gs);
    zero_range(out, 3*MP + 3*total, 6*MP, gt, gs);
    zero_range(out, 6*MP + total, 7*MP,   gt, gs);
  }
}

// ---------------- launch ----------------
extern "C" void kernel_launch(void* const* d_in, const int* in_sizes, int n_in,
                              void* d_out, int out_size) {
  const float* coords = nullptr;
  for (int i = 0; i < n_in; i++)
    if (in_sizes[i] == 3*NA) coords = (const float*)d_in[i];
  float* out = (float*)d_out;

  k_assign  <<<(NA + 255)/256, 256>>>(coords);            // cells + staging + bin reset
  k_sortcell<<<(NC + 7)/8, 256>>>();                      // per-cell id sort -> g_sp4
  k_pairs   <<<NC, 256>>>();                              // dual-atom smem pairs
  k_emit    <<<NBE_A + NBE_W + NB_TAIL, 256>>>(out);      // 4-way emit + flat-range tail
}